// round 1
// baseline (speedup 1.0000x reference)
#include <cuda_runtime.h>

#define BATCH 8192
#define IN_F  2048
#define OUT_F 2048

// Scratch: tanh(x) precomputed, and bias column-sums.
__device__ float g_T[(size_t)BATCH * IN_F];
__device__ float g_bias[OUT_F];

// ---------------------------------------------------------------------------
// Prologue: T = tanh(x), vectorized float4. Precise tanhf (error ~2 ulp).
// ---------------------------------------------------------------------------
__global__ void tanh_kernel(const float* __restrict__ x) {
    int i = (blockIdx.x * blockDim.x + threadIdx.x) * 4;
    float4 v = *reinterpret_cast<const float4*>(x + i);
    v.x = tanhf(v.x);
    v.y = tanhf(v.y);
    v.z = tanhf(v.z);
    v.w = tanhf(v.w);
    *reinterpret_cast<float4*>(g_T + i) = v;
}

__global__ void zero_bias_kernel() {
    int j = blockIdx.x * blockDim.x + threadIdx.x;
    if (j < OUT_F) g_bias[j] = 0.0f;
}

// bias[j] = sum_i B[i, j].  Grid (OUT_F/256, 32): each block reduces 64 rows
// for 256 columns (coalesced across threads), one atomicAdd per thread.
__global__ void colsum_kernel(const float* __restrict__ B) {
    int j  = blockIdx.x * 256 + threadIdx.x;
    int i0 = blockIdx.y * 64;
    float s = 0.0f;
    #pragma unroll 8
    for (int i = 0; i < 64; i++) {
        s += B[(size_t)(i0 + i) * OUT_F + j];
    }
    atomicAdd(&g_bias[j], s);
}

// ---------------------------------------------------------------------------
// GEMM: out[8192, 2048] = T @ W + bias
// 128x128 block tile, BK=16, 256 threads, 8x8 per-thread microtile.
// Inner product uses packed fma.rn.f32x2 (2 FMAs per issue on the fma pipe).
// Double-buffered shared memory, float4 global loads, no bounds checks
// (all dims divisible by tile sizes).
// ---------------------------------------------------------------------------
#define BM 128
#define BN 128
#define BK 16

__device__ __forceinline__ unsigned long long pack2(float a) {
    unsigned long long r;
    asm("mov.b64 %0, {%1, %1};" : "=l"(r) : "f"(a));
    return r;
}

__device__ __forceinline__ void fma2(unsigned long long& d,
                                     unsigned long long a,
                                     unsigned long long b) {
    asm("fma.rn.f32x2 %0, %1, %2, %0;" : "+l"(d) : "l"(a), "l"(b));
}

__global__ void __launch_bounds__(256, 1)
gemm_kernel(const float* __restrict__ Wm, float* __restrict__ out) {
    __shared__ __align__(16) float As[2][BK][BM];   // [k][m] (transposed store)
    __shared__ __align__(16) float Bs[2][BK][BN];   // [k][n]

    const int tid = threadIdx.x;
    const int tx  = tid & 15;      // 0..15 -> column group (8 cols each)
    const int ty  = tid >> 4;      // 0..15 -> row group    (8 rows each)

    const int rowBase = blockIdx.y * BM;
    const int colBase = blockIdx.x * BN;

    const float* Aptr = g_T + (size_t)rowBase * IN_F;   // [BM, IN_F]
    const float* Bptr = Wm + colBase;                   // [IN_F, OUT_F] slice

    // Loader mapping: 512 float4 per tile per operand; 2 per thread.
    // A: float4 f -> row = f>>2, k = (f&3)*4        (tile is BM x BK)
    // B: float4 f -> k   = f>>5, col = (f&31)*4     (tile is BK x BN)

    // ---- load tile 0 into buffer 0 ----
    #pragma unroll
    for (int s = 0; s < 2; s++) {
        int f  = tid + s * 256;
        int ar = f >> 2, ak = (f & 3) * 4;
        float4 v = *reinterpret_cast<const float4*>(Aptr + (size_t)ar * IN_F + ak);
        As[0][ak + 0][ar] = v.x;
        As[0][ak + 1][ar] = v.y;
        As[0][ak + 2][ar] = v.z;
        As[0][ak + 3][ar] = v.w;

        int bk = f >> 5, bc = (f & 31) * 4;
        float4 w = *reinterpret_cast<const float4*>(Bptr + (size_t)bk * OUT_F + bc);
        *reinterpret_cast<float4*>(&Bs[0][bk][bc]) = w;
    }
    __syncthreads();

    unsigned long long acc[8][4];   // 8 rows x 4 float2 (= 8 cols)
    #pragma unroll
    for (int i = 0; i < 8; i++)
        #pragma unroll
        for (int j = 0; j < 4; j++) acc[i][j] = 0ull;

    const int KT = IN_F / BK;   // 128

    for (int kt = 0; kt < KT; kt++) {
        const int buf = kt & 1;
        float4 apre[2], bpre[2];
        const bool pf = (kt + 1 < KT);

        if (pf) {
            const int koff = (kt + 1) * BK;
            #pragma unroll
            for (int s = 0; s < 2; s++) {
                int f  = tid + s * 256;
                int ar = f >> 2, ak = (f & 3) * 4;
                apre[s] = *reinterpret_cast<const float4*>(
                    Aptr + (size_t)ar * IN_F + koff + ak);
                int bk = f >> 5, bc = (f & 31) * 4;
                bpre[s] = *reinterpret_cast<const float4*>(
                    Bptr + (size_t)(koff + bk) * OUT_F + bc);
            }
        }

        #pragma unroll
        for (int k = 0; k < BK; k++) {
            float a_frag[8];
            *reinterpret_cast<float4*>(a_frag) =
                *reinterpret_cast<const float4*>(&As[buf][k][ty * 8]);
            *reinterpret_cast<float4*>(a_frag + 4) =
                *reinterpret_cast<const float4*>(&As[buf][k][ty * 8 + 4]);

            unsigned long long b_frag[4];
            const unsigned long long* bp =
                reinterpret_cast<const unsigned long long*>(&Bs[buf][k][tx * 8]);
            b_frag[0] = bp[0];
            b_frag[1] = bp[1];
            b_frag[2] = bp[2];
            b_frag[3] = bp[3];

            #pragma unroll
            for (int i = 0; i < 8; i++) {
                unsigned long long ap = pack2(a_frag[i]);
                #pragma unroll
                for (int j = 0; j < 4; j++) fma2(acc[i][j], ap, b_frag[j]);
            }
        }

        if (pf) {
            const int nbuf = buf ^ 1;
            #pragma unroll
            for (int s = 0; s < 2; s++) {
                int f  = tid + s * 256;
                int ar = f >> 2, ak = (f & 3) * 4;
                As[nbuf][ak + 0][ar] = apre[s].x;
                As[nbuf][ak + 1][ar] = apre[s].y;
                As[nbuf][ak + 2][ar] = apre[s].z;
                As[nbuf][ak + 3][ar] = apre[s].w;
                int bk = f >> 5, bc = (f & 31) * 4;
                *reinterpret_cast<float4*>(&Bs[nbuf][bk][bc]) = bpre[s];
            }
        }
        __syncthreads();
    }

    // ---- epilogue: add bias, store float4 ----
    const int row0 = rowBase + ty * 8;
    const int col0 = colBase + tx * 8;

    float bias[8];
    *reinterpret_cast<float4*>(bias) =
        *reinterpret_cast<const float4*>(g_bias + col0);
    *reinterpret_cast<float4*>(bias + 4) =
        *reinterpret_cast<const float4*>(g_bias + col0 + 4);

    #pragma unroll
    for (int i = 0; i < 8; i++) {
        float c[8];
        #pragma unroll
        for (int j = 0; j < 4; j++) {
            float2 p = *reinterpret_cast<float2*>(&acc[i][j]);
            c[2 * j + 0] = p.x + bias[2 * j + 0];
            c[2 * j + 1] = p.y + bias[2 * j + 1];
        }
        float* o = out + (size_t)(row0 + i) * OUT_F + col0;
        *reinterpret_cast<float4*>(o)     = *reinterpret_cast<float4*>(c);
        *reinterpret_cast<float4*>(o + 4) = *reinterpret_cast<float4*>(c + 4);
    }
}

// ---------------------------------------------------------------------------
extern "C" void kernel_launch(void* const* d_in, const int* in_sizes, int n_in,
                              void* d_out, int out_size) {
    const float* x = (const float*)d_in[0];
    const float* W = (const float*)d_in[1];
    const float* B = (const float*)d_in[2];
    float* out = (float*)d_out;

    tanh_kernel<<<(BATCH * IN_F) / (256 * 4), 256>>>(x);
    zero_bias_kernel<<<OUT_F / 256, 256>>>();
    colsum_kernel<<<dim3(OUT_F / 256, 32), 256>>>(B);
    gemm_kernel<<<dim3(OUT_F / BN, BATCH / BM), 256>>>(W, out);
}